// round 3
// baseline (speedup 1.0000x reference)
#include <cuda_runtime.h>

#define Bdim 16
#define Tdim 1024
#define Cdim 1024
#define T2 (Tdim + 2)
#define NROWS (Bdim * T2)
#define EPS 1e-5f
#define WARPS_PER_CTA 4
#define RPW 8   // rows per warp

// Warp-per-row speech embedder, 8 rows per warp with gamma/beta persisted in
// registers across rows (cuts L1 crossbar traffic ~35%).
__global__ void __launch_bounds__(WARPS_PER_CTA * 32)
embed_kernel(const float* __restrict__ x,
             const int*   __restrict__ lengths,
             const float* __restrict__ bos_emb,
             const float* __restrict__ eos_emb,
             const float* __restrict__ ln_s_g,
             const float* __restrict__ ln_s_b,
             const float* __restrict__ pos_table,
             const float* __restrict__ scale_p,
             const float* __restrict__ ln_e_g,
             const float* __restrict__ ln_e_b,
             float* __restrict__ out,
             long long out_size) {
    const int gwarp = blockIdx.x * WARPS_PER_CTA + (threadIdx.x >> 5);
    const int lane  = threadIdx.x & 31;
    const int row0  = gwarp * RPW;
    if (row0 >= NROWS) return;

    const float sc = scale_p[0];

    // Persist final-LN gamma/beta in registers for all RPW rows
    float4 g[8], bt[8];
    {
        const float4* gg = reinterpret_cast<const float4*>(ln_e_g);
        const float4* bb = reinterpret_cast<const float4*>(ln_e_b);
        #pragma unroll
        for (int c = 0; c < 8; c++) {
            g[c]  = gg[lane + 32 * c];
            bt[c] = bb[lane + 32 * c];
        }
    }

    const long long XSZ = (long long)NROWS * Cdim;
    const bool aux  = (out_size >= XSZ + (long long)NROWS);
    const bool aux2 = (out_size >= XSZ + (long long)NROWS + Bdim);

    #pragma unroll 1
    for (int r = 0; r < RPW; r++) {
        const int row = row0 + r;
        if (row >= NROWS) break;
        const int b  = row / T2;
        const int t2 = row % T2;
        const int l  = lengths[b];

        float4 v[8];

        if (t2 == 0 || t2 == l + 1) {
            // Inline layernorm of the special embedding (rare: ~32 of 16416 rows)
            const float4* src = reinterpret_cast<const float4*>((t2 == 0) ? bos_emb : eos_emb);
            float s = 0.f, s2 = 0.f;
            #pragma unroll
            for (int c = 0; c < 8; c++) {
                v[c] = src[lane + 32 * c];
                s  += v[c].x + v[c].y + v[c].z + v[c].w;
                s2 += v[c].x*v[c].x + v[c].y*v[c].y + v[c].z*v[c].z + v[c].w*v[c].w;
            }
            #pragma unroll
            for (int o = 16; o > 0; o >>= 1) {
                s  += __shfl_xor_sync(0xffffffffu, s,  o);
                s2 += __shfl_xor_sync(0xffffffffu, s2, o);
            }
            const float mu  = s * (1.0f / Cdim);
            const float var = s2 * (1.0f / Cdim) - mu * mu;
            const float inv = rsqrtf(var + EPS);
            const float4* sg = reinterpret_cast<const float4*>(ln_s_g);
            const float4* sb = reinterpret_cast<const float4*>(ln_s_b);
            #pragma unroll
            for (int c = 0; c < 8; c++) {
                const float4 gs = sg[lane + 32 * c];
                const float4 bs = sb[lane + 32 * c];
                v[c].x = (v[c].x - mu) * inv * gs.x + bs.x;
                v[c].y = (v[c].y - mu) * inv * gs.y + bs.y;
                v[c].z = (v[c].z - mu) * inv * gs.z + bs.z;
                v[c].w = (v[c].w - mu) * inv * gs.w + bs.w;
            }
        } else if (t2 >= 1 && t2 <= l) {
            const float4* xr = reinterpret_cast<const float4*>(
                x + ((size_t)(b * Tdim + (t2 - 1))) * Cdim);
            #pragma unroll
            for (int c = 0; c < 8; c++) v[c] = xr[lane + 32 * c];
        } else {
            #pragma unroll
            for (int c = 0; c < 8; c++) v[c] = make_float4(0.f, 0.f, 0.f, 0.f);
        }

        // Positional embedding: nonpad -> row t2+2, pad -> PAD_IDX row (1)
        const int pos = (t2 < l + 2) ? (t2 + 2) : 1;
        const float4* per = reinterpret_cast<const float4*>(pos_table + (size_t)pos * Cdim);

        float s = 0.f, s2 = 0.f;
        #pragma unroll
        for (int c = 0; c < 8; c++) {
            const float4 p = per[lane + 32 * c];
            v[c].x = v[c].x * sc + p.x;
            v[c].y = v[c].y * sc + p.y;
            v[c].z = v[c].z * sc + p.z;
            v[c].w = v[c].w * sc + p.w;
            s  += v[c].x + v[c].y + v[c].z + v[c].w;
            s2 += v[c].x*v[c].x + v[c].y*v[c].y + v[c].z*v[c].z + v[c].w*v[c].w;
        }
        #pragma unroll
        for (int o = 16; o > 0; o >>= 1) {
            s  += __shfl_xor_sync(0xffffffffu, s,  o);
            s2 += __shfl_xor_sync(0xffffffffu, s2, o);
        }
        const float mu  = s * (1.0f / Cdim);
        const float var = s2 * (1.0f / Cdim) - mu * mu;
        const float inv = rsqrtf(var + EPS);

        float4* orow = reinterpret_cast<float4*>(out + (size_t)row * Cdim);
        #pragma unroll
        for (int c = 0; c < 8; c++) {
            float4 o;
            o.x = (v[c].x - mu) * inv * g[c].x + bt[c].x;
            o.y = (v[c].y - mu) * inv * g[c].y + bt[c].y;
            o.z = (v[c].z - mu) * inv * g[c].z + bt[c].z;
            o.w = (v[c].w - mu) * inv * g[c].w + bt[c].w;
            orow[lane + 32 * c] = o;
        }

        // Auxiliary outputs appended after the main tensor if the buffer has room
        if (aux) {
            if (lane == 0) out[XSZ + row] = (t2 >= l + 2) ? 1.0f : 0.0f;
            if (lane == 1 && t2 == 0 && aux2)
                out[XSZ + (long long)NROWS + b] = (float)(l + 2);
        }
    }
}

extern "C" void kernel_launch(void* const* d_in, const int* in_sizes, int n_in,
                              void* d_out, int out_size) {
    const float* x         = (const float*)d_in[0];
    const int*   lengths   = (const int*)  d_in[1];
    const float* bos_emb   = (const float*)d_in[2];
    const float* eos_emb   = (const float*)d_in[3];
    const float* ln_s_g    = (const float*)d_in[4];
    const float* ln_s_b    = (const float*)d_in[5];
    const float* pos_table = (const float*)d_in[6];
    const float* scale     = (const float*)d_in[7];
    const float* ln_e_g    = (const float*)d_in[8];
    const float* ln_e_b    = (const float*)d_in[9];
    float* out = (float*)d_out;

    const int rows_per_cta = WARPS_PER_CTA * RPW;
    const int grid = (NROWS + rows_per_cta - 1) / rows_per_cta;
    embed_kernel<<<grid, WARPS_PER_CTA * 32>>>(
        x, lengths, bos_emb, eos_emb, ln_s_g, ln_s_b,
        pos_table, scale, ln_e_g, ln_e_b, out, (long long)out_size);
}

// round 4
// speedup vs baseline: 1.2281x; 1.2281x over previous
#include <cuda_runtime.h>

#define Bdim 16
#define Tdim 1024
#define Cdim 1024
#define T2 (Tdim + 2)
#define NROWS (Bdim * T2)
#define EPS 1e-5f
#define WARPS_PER_CTA 8

// Fused warp-per-row speech embedder.
// Each warp owns one output row (b, t2): 1024 channels = 8 x float4 per lane.
// No __syncthreads; reductions are warp shuffles only.
// __launch_bounds__(256, 4): cap regs at 64 so 4 CTAs (32 warps) fit per SM.
__global__ void __launch_bounds__(256, 4)
embed_kernel(const float* __restrict__ x,
             const int*   __restrict__ lengths,
             const float* __restrict__ bos_emb,
             const float* __restrict__ eos_emb,
             const float* __restrict__ ln_s_g,
             const float* __restrict__ ln_s_b,
             const float* __restrict__ pos_table,
             const float* __restrict__ scale_p,
             const float* __restrict__ ln_e_g,
             const float* __restrict__ ln_e_b,
             float* __restrict__ out,
             long long out_size) {
    const int gwarp = (blockIdx.x * WARPS_PER_CTA) + (threadIdx.x >> 5);
    if (gwarp >= NROWS) return;
    const int lane = threadIdx.x & 31;
    const int b  = gwarp / T2;
    const int t2 = gwarp % T2;
    const int l  = lengths[b];
    const float sc = scale_p[0];

    float4 v[8];

    if (t2 == 0 || t2 == l + 1) {
        // Inline layernorm of the special embedding (only ~32 of 16416 rows)
        const float4* src = reinterpret_cast<const float4*>((t2 == 0) ? bos_emb : eos_emb);
        float s = 0.f, s2 = 0.f;
        #pragma unroll
        for (int c = 0; c < 8; c++) {
            v[c] = src[lane + 32 * c];
            s  += v[c].x + v[c].y + v[c].z + v[c].w;
            s2 += v[c].x*v[c].x + v[c].y*v[c].y + v[c].z*v[c].z + v[c].w*v[c].w;
        }
        #pragma unroll
        for (int o = 16; o > 0; o >>= 1) {
            s  += __shfl_xor_sync(0xffffffffu, s,  o);
            s2 += __shfl_xor_sync(0xffffffffu, s2, o);
        }
        const float mu  = s * (1.0f / Cdim);
        const float var = s2 * (1.0f / Cdim) - mu * mu;
        const float inv = rsqrtf(var + EPS);
        const float4* sg = reinterpret_cast<const float4*>(ln_s_g);
        const float4* sb = reinterpret_cast<const float4*>(ln_s_b);
        #pragma unroll
        for (int c = 0; c < 8; c++) {
            const float4 gs = sg[lane + 32 * c];
            const float4 bs = sb[lane + 32 * c];
            v[c].x = (v[c].x - mu) * inv * gs.x + bs.x;
            v[c].y = (v[c].y - mu) * inv * gs.y + bs.y;
            v[c].z = (v[c].z - mu) * inv * gs.z + bs.z;
            v[c].w = (v[c].w - mu) * inv * gs.w + bs.w;
        }
    } else if (t2 >= 1 && t2 <= l) {
        const float4* xr = reinterpret_cast<const float4*>(
            x + ((size_t)(b * Tdim + (t2 - 1))) * Cdim);
        #pragma unroll
        for (int c = 0; c < 8; c++) v[c] = xr[lane + 32 * c];
    } else {
        #pragma unroll
        for (int c = 0; c < 8; c++) v[c] = make_float4(0.f, 0.f, 0.f, 0.f);
    }

    // Positional embedding: nonpad -> row t2+2, pad -> PAD_IDX row (1)
    const int pos = (t2 < l + 2) ? (t2 + 2) : 1;
    const float4* per = reinterpret_cast<const float4*>(pos_table + (size_t)pos * Cdim);

    float s = 0.f, s2 = 0.f;
    #pragma unroll
    for (int c = 0; c < 8; c++) {
        const float4 p = per[lane + 32 * c];
        v[c].x = v[c].x * sc + p.x;
        v[c].y = v[c].y * sc + p.y;
        v[c].z = v[c].z * sc + p.z;
        v[c].w = v[c].w * sc + p.w;
        s  += v[c].x + v[c].y + v[c].z + v[c].w;
        s2 += v[c].x*v[c].x + v[c].y*v[c].y + v[c].z*v[c].z + v[c].w*v[c].w;
    }
    #pragma unroll
    for (int o = 16; o > 0; o >>= 1) {
        s  += __shfl_xor_sync(0xffffffffu, s,  o);
        s2 += __shfl_xor_sync(0xffffffffu, s2, o);
    }
    const float mu  = s * (1.0f / Cdim);
    const float var = s2 * (1.0f / Cdim) - mu * mu;
    const float inv = rsqrtf(var + EPS);

    const float4* gg = reinterpret_cast<const float4*>(ln_e_g);
    const float4* bb = reinterpret_cast<const float4*>(ln_e_b);
    float4* orow = reinterpret_cast<float4*>(out + (size_t)gwarp * Cdim);
    #pragma unroll
    for (int c = 0; c < 8; c++) {
        const float4 g  = gg[lane + 32 * c];
        const float4 bt = bb[lane + 32 * c];
        float4 o;
        o.x = (v[c].x - mu) * inv * g.x + bt.x;
        o.y = (v[c].y - mu) * inv * g.y + bt.y;
        o.z = (v[c].z - mu) * inv * g.z + bt.z;
        o.w = (v[c].w - mu) * inv * g.w + bt.w;
        orow[lane + 32 * c] = o;
    }

    // Auxiliary outputs appended after the main tensor if the buffer has room
    const long long XSZ = (long long)NROWS * Cdim;
    if (out_size >= XSZ + (long long)NROWS) {
        if (lane == 0) out[XSZ + gwarp] = (t2 >= l + 2) ? 1.0f : 0.0f;
        if (lane == 1 && t2 == 0 && out_size >= XSZ + (long long)NROWS + Bdim)
            out[XSZ + (long long)NROWS + b] = (float)(l + 2);
    }
}

extern "C" void kernel_launch(void* const* d_in, const int* in_sizes, int n_in,
                              void* d_out, int out_size) {
    const float* x         = (const float*)d_in[0];
    const int*   lengths   = (const int*)  d_in[1];
    const float* bos_emb   = (const float*)d_in[2];
    const float* eos_emb   = (const float*)d_in[3];
    const float* ln_s_g    = (const float*)d_in[4];
    const float* ln_s_b    = (const float*)d_in[5];
    const float* pos_table = (const float*)d_in[6];
    const float* scale     = (const float*)d_in[7];
    const float* ln_e_g    = (const float*)d_in[8];
    const float* ln_e_b    = (const float*)d_in[9];
    float* out = (float*)d_out;

    const int grid = (NROWS + WARPS_PER_CTA - 1) / WARPS_PER_CTA;
    embed_kernel<<<grid, WARPS_PER_CTA * 32>>>(
        x, lengths, bos_emb, eos_emb, ln_s_g, ln_s_b,
        pos_table, scale, ln_e_g, ln_e_b, out, (long long)out_size);
}

// round 5
// speedup vs baseline: 1.2911x; 1.0513x over previous
#include <cuda_runtime.h>

#define Bdim 16
#define Tdim 1024
#define Cdim 1024
#define T2 (Tdim + 2)
#define NROWS (Bdim * T2)
#define EPS 1e-5f
#define NT 64          // threads per CTA (one row per CTA, 2 warps)
#define VPT 4          // float4 per thread: 64*4*4 = 1024 channels

// CTA-per-row speech embedder: 64 threads, 16 floats/thread (low reg pressure
// -> high occupancy AND full load MLP). One cheap 2-warp smem reduction per row.

__device__ __forceinline__ float2 row_reduce64(float s, float s2, volatile float* sm) {
    const int lane = threadIdx.x & 31;
    const int w    = threadIdx.x >> 5;
    #pragma unroll
    for (int o = 16; o > 0; o >>= 1) {
        s  += __shfl_xor_sync(0xffffffffu, s,  o);
        s2 += __shfl_xor_sync(0xffffffffu, s2, o);
    }
    __syncthreads();               // protect smem from previous use
    if (lane == 0) { sm[w * 2] = s; sm[w * 2 + 1] = s2; }
    __syncthreads();
    return make_float2(sm[0] + sm[2], sm[1] + sm[3]);
}

__global__ void __launch_bounds__(NT)
embed_kernel(const float* __restrict__ x,
             const int*   __restrict__ lengths,
             const float* __restrict__ bos_emb,
             const float* __restrict__ eos_emb,
             const float* __restrict__ ln_s_g,
             const float* __restrict__ ln_s_b,
             const float* __restrict__ pos_table,
             const float* __restrict__ scale_p,
             const float* __restrict__ ln_e_g,
             const float* __restrict__ ln_e_b,
             float* __restrict__ out,
             long long out_size) {
    const int row = blockIdx.x;          // 0 .. NROWS-1
    const int tid = threadIdx.x;         // 0 .. 63
    const int b   = row / T2;
    const int t2  = row % T2;
    const int l   = lengths[b];
    const float sc = scale_p[0];

    __shared__ float sm[4];

    float4 v[VPT];

    if (t2 == 0 || t2 == l + 1) {
        // Inline layernorm of the special embedding (~32 of 16416 rows)
        const float4* src = reinterpret_cast<const float4*>((t2 == 0) ? bos_emb : eos_emb);
        float s = 0.f, s2 = 0.f;
        #pragma unroll
        for (int c = 0; c < VPT; c++) {
            v[c] = src[tid + NT * c];
            s  += v[c].x + v[c].y + v[c].z + v[c].w;
            s2 += v[c].x*v[c].x + v[c].y*v[c].y + v[c].z*v[c].z + v[c].w*v[c].w;
        }
        const float2 r = row_reduce64(s, s2, sm);
        const float mu  = r.x * (1.0f / Cdim);
        const float var = r.y * (1.0f / Cdim) - mu * mu;
        const float inv = rsqrtf(var + EPS);
        const float4* sg = reinterpret_cast<const float4*>(ln_s_g);
        const float4* sb = reinterpret_cast<const float4*>(ln_s_b);
        #pragma unroll
        for (int c = 0; c < VPT; c++) {
            const float4 gs = sg[tid + NT * c];
            const float4 bs = sb[tid + NT * c];
            v[c].x = (v[c].x - mu) * inv * gs.x + bs.x;
            v[c].y = (v[c].y - mu) * inv * gs.y + bs.y;
            v[c].z = (v[c].z - mu) * inv * gs.z + bs.z;
            v[c].w = (v[c].w - mu) * inv * gs.w + bs.w;
        }
    } else if (t2 >= 1 && t2 <= l) {
        const float4* xr = reinterpret_cast<const float4*>(
            x + ((size_t)(b * Tdim + (t2 - 1))) * Cdim);
        #pragma unroll
        for (int c = 0; c < VPT; c++) v[c] = xr[tid + NT * c];
    } else {
        #pragma unroll
        for (int c = 0; c < VPT; c++) v[c] = make_float4(0.f, 0.f, 0.f, 0.f);
    }

    // Positional embedding: nonpad -> row t2+2, pad -> PAD_IDX row (1)
    const int pos = (t2 < l + 2) ? (t2 + 2) : 1;
    const float4* per = reinterpret_cast<const float4*>(pos_table + (size_t)pos * Cdim);

    float s = 0.f, s2 = 0.f;
    #pragma unroll
    for (int c = 0; c < VPT; c++) {
        const float4 p = per[tid + NT * c];
        v[c].x = v[c].x * sc + p.x;
        v[c].y = v[c].y * sc + p.y;
        v[c].z = v[c].z * sc + p.z;
        v[c].w = v[c].w * sc + p.w;
        s  += v[c].x + v[c].y + v[c].z + v[c].w;
        s2 += v[c].x*v[c].x + v[c].y*v[c].y + v[c].z*v[c].z + v[c].w*v[c].w;
    }
    const float2 r = row_reduce64(s, s2, sm);
    const float mu  = r.x * (1.0f / Cdim);
    const float var = r.y * (1.0f / Cdim) - mu * mu;
    const float inv = rsqrtf(var + EPS);

    const float4* gg = reinterpret_cast<const float4*>(ln_e_g);
    const float4* bb = reinterpret_cast<const float4*>(ln_e_b);
    float4* orow = reinterpret_cast<float4*>(out + (size_t)row * Cdim);
    #pragma unroll
    for (int c = 0; c < VPT; c++) {
        const float4 g  = gg[tid + NT * c];
        const float4 bt = bb[tid + NT * c];
        float4 o;
        o.x = (v[c].x - mu) * inv * g.x + bt.x;
        o.y = (v[c].y - mu) * inv * g.y + bt.y;
        o.z = (v[c].z - mu) * inv * g.z + bt.z;
        o.w = (v[c].w - mu) * inv * g.w + bt.w;
        orow[tid + NT * c] = o;
    }

    // Auxiliary outputs appended after the main tensor if the buffer has room
    const long long XSZ = (long long)NROWS * Cdim;
    if (out_size >= XSZ + (long long)NROWS) {
        if (tid == 0) out[XSZ + row] = (t2 >= l + 2) ? 1.0f : 0.0f;
        if (tid == 1 && t2 == 0 && out_size >= XSZ + (long long)NROWS + Bdim)
            out[XSZ + (long long)NROWS + b] = (float)(l + 2);
    }
}

extern "C" void kernel_launch(void* const* d_in, const int* in_sizes, int n_in,
                              void* d_out, int out_size) {
    const float* x         = (const float*)d_in[0];
    const int*   lengths   = (const int*)  d_in[1];
    const float* bos_emb   = (const float*)d_in[2];
    const float* eos_emb   = (const float*)d_in[3];
    const float* ln_s_g    = (const float*)d_in[4];
    const float* ln_s_b    = (const float*)d_in[5];
    const float* pos_table = (const float*)d_in[6];
    const float* scale     = (const float*)d_in[7];
    const float* ln_e_g    = (const float*)d_in[8];
    const float* ln_e_b    = (const float*)d_in[9];
    float* out = (float*)d_out;

    embed_kernel<<<NROWS, NT>>>(
        x, lengths, bos_emb, eos_emb, ln_s_g, ln_s_b,
        pos_table, scale, ln_e_g, ln_e_b, out, (long long)out_size);
}